// round 7
// baseline (speedup 1.0000x reference)
#include <cuda_runtime.h>
#include <cstdint>

// ============================================================================
// SensorCalibration. R7: split-accumulator contraction (chain depth 9->5),
// folded Adam constants (M=m/0.1, V=v/0.001; scales absorbed into the
// bias-correction table), packed-u64 shfl epilogue in reduce.
// R6 was 103.0us (adam 90.4, reduce ~12.6).
// ============================================================================

#define NSENS 17
#define NT    16384
#define ROWLEN (NSENS * 9)
#define NBLK  8
#define NITER 450

__device__ float gPart[NSENS][NBLK][81];

// ---------------------------------------------------------------------------
// fast approx + packed f32x2 intrinsics
// ---------------------------------------------------------------------------
__device__ __forceinline__ float f_rsqrt(float x) { float r; asm("rsqrt.approx.f32 %0, %1;" : "=f"(r) : "f"(x)); return r; }
__device__ __forceinline__ float f_sin(float x)   { float r; asm("sin.approx.f32 %0, %1;"   : "=f"(r) : "f"(x)); return r; }
__device__ __forceinline__ float f_cos(float x)   { float r; asm("cos.approx.f32 %0, %1;"   : "=f"(r) : "f"(x)); return r; }
__device__ __forceinline__ float f_rcp(float x)   { float r; asm("rcp.approx.f32 %0, %1;"   : "=f"(r) : "f"(x)); return r; }
__device__ __forceinline__ float f_ex2(float x)   { float r; asm("ex2.approx.f32 %0, %1;"   : "=f"(r) : "f"(x)); return r; }

typedef unsigned long long u64;
__device__ __forceinline__ u64 pk2(float lo, float hi) {
    u64 r; asm("mov.b64 %0, {%1, %2};" : "=l"(r) : "f"(lo), "f"(hi)); return r;
}
__device__ __forceinline__ void upk2(float& lo, float& hi, u64 v) {
    asm("mov.b64 {%0, %1}, %2;" : "=f"(lo), "=f"(hi) : "l"(v));
}
__device__ __forceinline__ u64 fma2(u64 a, u64 b, u64 c) {
    u64 d; asm("fma.rn.f32x2 %0, %1, %2, %3;" : "=l"(d) : "l"(a), "l"(b), "l"(c)); return d;
}
__device__ __forceinline__ u64 mul2(u64 a, u64 b) {
    u64 d; asm("mul.rn.f32x2 %0, %1, %2;" : "=l"(d) : "l"(a), "l"(b)); return d;
}
__device__ __forceinline__ u64 add2(u64 a, u64 b) {
    u64 d; asm("add.rn.f32x2 %0, %1, %2;" : "=l"(d) : "l"(a), "l"(b)); return d;
}

// ---------------------------------------------------------------------------
// Kernel 1: per-block partials of M[n][jk][il] = sum_t org[t,n,jk]*trg[t,n,il]
// ---------------------------------------------------------------------------
__global__ void reduce_kernel(const float* __restrict__ org,
                              const float* __restrict__ trg) {
    const int n    = blockIdx.y;
    const int base = blockIdx.x * blockDim.x + threadIdx.x;   // 0..2047

    u64   accP[9][4];
    float acc8[9];
#pragma unroll
    for (int j = 0; j < 9; j++) {
#pragma unroll
        for (int p = 0; p < 4; p++) accP[j][p] = 0ull;
        acc8[j] = 0.0f;
    }

#pragma unroll
    for (int kk = 0; kk < 8; kk++) {
        const int t = base + kk * 2048;
        const float* a = org + (size_t)t * ROWLEN + n * 9;
        const float* b = trg + (size_t)t * ROWLEN + n * 9;
        float av[9], bv[9];
#pragma unroll
        for (int i = 0; i < 9; i++) { av[i] = a[i]; bv[i] = b[i]; }
        u64 bp[4];
#pragma unroll
        for (int p = 0; p < 4; p++) bp[p] = pk2(bv[2 * p], bv[2 * p + 1]);
#pragma unroll
        for (int j = 0; j < 9; j++) {
            u64 ad = pk2(av[j], av[j]);
#pragma unroll
            for (int p = 0; p < 4; p++) accP[j][p] = fma2(ad, bp[p], accP[j][p]);
            acc8[j] = fmaf(av[j], bv[8], acc8[j]);
        }
    }

    // packed warp tree (64-bit shfl + add.f32x2), then scalar tail elems
    const int lane = threadIdx.x & 31;
    const int wid  = threadIdx.x >> 5;
    __shared__ float sW[8][81];
#pragma unroll
    for (int j = 0; j < 9; j++) {
#pragma unroll
        for (int p = 0; p < 4; p++) {
            u64 v = accP[j][p];
#pragma unroll
            for (int d = 16; d >= 1; d >>= 1)
                v = add2(v, __shfl_xor_sync(0xFFFFFFFFu, v, d));
            if (lane == 0) {
                float lo, hi; upk2(lo, hi, v);
                sW[wid][j * 9 + 2 * p]     = lo;
                sW[wid][j * 9 + 2 * p + 1] = hi;
            }
        }
        float s8 = acc8[j];
#pragma unroll
        for (int d = 16; d >= 1; d >>= 1)
            s8 += __shfl_xor_sync(0xFFFFFFFFu, s8, d);
        if (lane == 0) sW[wid][j * 9 + 8] = s8;
    }
    __syncthreads();
    if (threadIdx.x < 81) {
        float s = 0.0f;
#pragma unroll
        for (int w = 0; w < 8; w++) s += sW[w][threadIdx.x];
        gPart[n][blockIdx.x][threadIdx.x] = s;
    }
}

// ---------------------------------------------------------------------------
// Threefry2x32-20, key (0,1), partitionable path: bits = o0 ^ o1.
// ---------------------------------------------------------------------------
__device__ __forceinline__ uint32_t rotl32(uint32_t v, uint32_t d) {
    return (v << d) | (v >> (32u - d));
}

__device__ void threefry_01(uint32_t x0, uint32_t x1, uint32_t& o0, uint32_t& o1) {
    const uint32_t k0 = 0u, k1 = 1u;
    const uint32_t k2 = k0 ^ k1 ^ 0x1BD11BDAu;
    x0 += k0; x1 += k1;
    x0 += x1; x1 = rotl32(x1, 13); x1 ^= x0;
    x0 += x1; x1 = rotl32(x1, 15); x1 ^= x0;
    x0 += x1; x1 = rotl32(x1, 26); x1 ^= x0;
    x0 += x1; x1 = rotl32(x1,  6); x1 ^= x0;
    x0 += k1; x1 += k2 + 1u;
    x0 += x1; x1 = rotl32(x1, 17); x1 ^= x0;
    x0 += x1; x1 = rotl32(x1, 29); x1 ^= x0;
    x0 += x1; x1 = rotl32(x1, 16); x1 ^= x0;
    x0 += x1; x1 = rotl32(x1, 24); x1 ^= x0;
    x0 += k2; x1 += k0 + 2u;
    x0 += x1; x1 = rotl32(x1, 13); x1 ^= x0;
    x0 += x1; x1 = rotl32(x1, 15); x1 ^= x0;
    x0 += x1; x1 = rotl32(x1, 26); x1 ^= x0;
    x0 += x1; x1 = rotl32(x1,  6); x1 ^= x0;
    x0 += k0; x1 += k1 + 3u;
    x0 += x1; x1 = rotl32(x1, 17); x1 ^= x0;
    x0 += x1; x1 = rotl32(x1, 29); x1 ^= x0;
    x0 += x1; x1 = rotl32(x1, 16); x1 ^= x0;
    x0 += x1; x1 = rotl32(x1, 24); x1 ^= x0;
    x0 += k1; x1 += k2 + 4u;
    x0 += x1; x1 = rotl32(x1, 13); x1 ^= x0;
    x0 += x1; x1 = rotl32(x1, 15); x1 ^= x0;
    x0 += x1; x1 = rotl32(x1, 26); x1 ^= x0;
    x0 += x1; x1 = rotl32(x1,  6); x1 ^= x0;
    x0 += k2; x1 += k0 + 5u;
    o0 = x0; o1 = x1;
}

__device__ float ang_init(int f) {
    uint32_t o0, o1;
    threefry_01(0u, (uint32_t)f, o0, o1);
    uint32_t bits = o0 ^ o1;
    uint32_t fb = (bits >> 9) | 0x3F800000u;
    return __uint_as_float(fb) - 1.0f;
}

// ---------------------------------------------------------------------------
// Kernel 2: 450 Adam iterations, one thread per sensor.
// 10 functionals of C (tD, w, S) in 5 packed streams, each split into two
// accumulator halves for ILP. Adam state kept unscaled: M = m/0.1 (so
// M = 0.9M + g), V = v/0.001 (V = 0.999V + g^2); the 0.1 / 0.001 scales are
// folded into the per-iteration table.
// ---------------------------------------------------------------------------
__global__ void __launch_bounds__(32, 1) adam_kernel(float* __restrict__ out) {
    const int n = threadIdx.x;

    // tab.x = lr_t * 0.1 / (1-0.9^t),  tab.y = 0.001 / (1-0.999^t)
    __shared__ float2 sTab[NITER];
    {
        const float l2_09   = -0.15200309344504997f;   // log2(0.9)
        const float l2_0999 = -0.0014434504088372195f; // log2(0.999)
        for (int t = threadIdx.x; t < NITER; t += 32) {
            float tf = (float)(t + 1);
            float p1 = f_ex2(tf * l2_09);
            float p2 = f_ex2(tf * l2_0999);
            float lr = (t < 150) ? 0.01f : ((t < 300) ? 0.009f : 0.0081f);
            sTab[t].x = lr * 0.1f * f_rcp(1.0f - p1);
            sTab[t].y = 0.001f * f_rcp(1.0f - p2);
        }
    }
    __syncwarp();

    if (n >= NSENS) return;

    double Md[81];
#pragma unroll
    for (int e = 0; e < 81; e++) {
        double s = 0.0;
#pragma unroll
        for (int b = 0; b < NBLK; b++) s += (double)gPart[n][b][e];
        Md[e] = s;
    }

#define MSF(p, k, q, l) \
    (-20.0f * (float)(Md[(3*(p)+(k))*9 + 3*(q)+(l)] + Md[(3*(k)+(p))*9 + 3*(l)+(q)]))

    // packed coefficient streams over j = 3k+l:
    // PA=(T,Wx)  PB=(Wy,Wz)  PC=(S00,S01)  PD=(S02,S11)  PE=(S12,S22)
    u64 PA[9], PB[9], PC[9], PD[9], PE[9];
#pragma unroll
    for (int k = 0; k < 3; k++)
#pragma unroll
        for (int l = 0; l < 3; l++) {
            int j = 3 * k + l;
            float T  = MSF(0,k,0,l) + MSF(1,k,1,l) + MSF(2,k,2,l);
            float Wx = MSF(2,k,1,l) - MSF(1,k,2,l);
            float Wy = MSF(0,k,2,l) - MSF(2,k,0,l);
            float Wz = MSF(1,k,0,l) - MSF(0,k,1,l);
            float S00 = 2.0f * MSF(0,k,0,l);
            float S11 = 2.0f * MSF(1,k,1,l);
            float S22 = 2.0f * MSF(2,k,2,l);
            float S01 = MSF(0,k,1,l) + MSF(1,k,0,l);
            float S02 = MSF(0,k,2,l) + MSF(2,k,0,l);
            float S12 = MSF(1,k,2,l) + MSF(2,k,1,l);
            PA[j] = pk2(T,  Wx);
            PB[j] = pk2(Wy, Wz);
            PC[j] = pk2(S00, S01);
            PD[j] = pk2(S02, S11);
            PE[j] = pk2(S12, S22);
        }
#undef MSF

    float rx = ang_init(3 * n + 0);
    float ry = ang_init(3 * n + 1);
    float rz = ang_init(3 * n + 2);
    float Mx = 0.f, My = 0.f, Mz = 0.f;    // m / 0.1
    float Vx = 0.f, Vy = 0.f, Vz = 0.f;    // v / 0.001

#pragma unroll 1
    for (int it = 0; it < NITER; it++) {
        float2 tab = sTab[it];

        float th2 = fmaxf(fmaf(rx, rx, fmaf(ry, ry, rz * rz)), 1e-24f);
        float inv = f_rsqrt(th2);
        float th  = th2 * inv;
        float kx = rx * inv, ky = ry * inv, kz = rz * inv;
        float s = f_sin(th);
        float c = f_cos(th);
        float o = 1.0f - c;

        float okx = o * kx, oky = o * ky, okz = o * kz;
        float skx = s * kx, sky = s * ky, skz = s * kz;
        float c0 = fmaf(okx, kx, c);
        float c1e = fmaf(okx, ky, -skz);
        float c2 = fmaf(okx, kz,  sky);
        float c3 = fmaf(oky, kx,  skz);
        float c4 = fmaf(oky, ky, c);
        float c5 = fmaf(oky, kz, -skx);
        float c6 = fmaf(okz, kx, -sky);
        float c7 = fmaf(okz, ky,  skx);
        float c8 = fmaf(okz, kz, c);
        u64 Cd[9];
        Cd[0] = pk2(c0, c0); Cd[1] = pk2(c1e, c1e); Cd[2] = pk2(c2, c2);
        Cd[3] = pk2(c3, c3); Cd[4] = pk2(c4, c4);  Cd[5] = pk2(c5, c5);
        Cd[6] = pk2(c6, c6); Cd[7] = pk2(c7, c7);  Cd[8] = pk2(c8, c8);

        // 5 streams x 2 accumulator halves (depth 5 instead of 9)
        u64 aA0 = mul2(PA[0], Cd[0]), aA1 = mul2(PA[5], Cd[5]);
        u64 aB0 = mul2(PB[0], Cd[0]), aB1 = mul2(PB[5], Cd[5]);
        u64 aC0 = mul2(PC[0], Cd[0]), aC1 = mul2(PC[5], Cd[5]);
        u64 aD0 = mul2(PD[0], Cd[0]), aD1 = mul2(PD[5], Cd[5]);
        u64 aE0 = mul2(PE[0], Cd[0]), aE1 = mul2(PE[5], Cd[5]);
#pragma unroll
        for (int j = 1; j < 5; j++) {
            aA0 = fma2(PA[j], Cd[j], aA0);
            aB0 = fma2(PB[j], Cd[j], aB0);
            aC0 = fma2(PC[j], Cd[j], aC0);
            aD0 = fma2(PD[j], Cd[j], aD0);
            aE0 = fma2(PE[j], Cd[j], aE0);
        }
#pragma unroll
        for (int j = 6; j < 9; j++) {
            aA1 = fma2(PA[j], Cd[j], aA1);
            aB1 = fma2(PB[j], Cd[j], aB1);
            aC1 = fma2(PC[j], Cd[j], aC1);
            aD1 = fma2(PD[j], Cd[j], aD1);
            aE1 = fma2(PE[j], Cd[j], aE1);
        }
        u64 aA = add2(aA0, aA1);
        u64 aB = add2(aB0, aB1);
        u64 aC = add2(aC0, aC1);
        u64 aD = add2(aD0, aD1);
        u64 aE = add2(aE0, aE1);

        float tD, wx, wy, wz, S00, S01, S02, S11, S12, S22;
        upk2(tD,  wx,  aA);
        upk2(wy,  wz,  aB);
        upk2(S00, S01, aC);
        upk2(S02, S11, aD);
        upk2(S12, S22, aE);

        float vx = fmaf(S00, kx, fmaf(S01, ky, S02 * kz));
        float vy = fmaf(S01, kx, fmaf(S11, ky, S12 * kz));
        float vz = fmaf(S02, kx, fmaf(S12, ky, S22 * kz));
        float q2 = fmaf(kx, vx, fmaf(ky, vy, kz * vz));
        float kw = fmaf(kx, wx, fmaf(ky, wy, kz * wz));

        float si = s * inv;
        float oi = o * inv;
        float alpha = fmaf(-s, tD,
                      fmaf(c - si, kw, fmaf(0.5f, s, -oi) * q2));

        float gx = fmaf(kx, alpha, fmaf(si, wx, oi * vx));
        float gy = fmaf(ky, alpha, fmaf(si, wy, oi * vy));
        float gz = fmaf(kz, alpha, fmaf(si, wz, oi * vz));

        Mx = fmaf(0.9f, Mx, gx);
        My = fmaf(0.9f, My, gy);
        Mz = fmaf(0.9f, Mz, gz);
        Vx = fmaf(0.999f, Vx, gx * gx);
        Vy = fmaf(0.999f, Vy, gy * gy);
        Vz = fmaf(0.999f, Vz, gz * gz);

        float rsx = f_rsqrt(fmaf(Vx, tab.y, 1e-30f));
        float rsy = f_rsqrt(fmaf(Vy, tab.y, 1e-30f));
        float rsz = f_rsqrt(fmaf(Vz, tab.y, 1e-30f));
        rx = fmaf(-(tab.x * Mx), rsx, rx);
        ry = fmaf(-(tab.x * My), rsy, ry);
        rz = fmaf(-(tab.x * Mz), rsz, rz);
    }

    out[3 * n + 0] = rx;
    out[3 * n + 1] = ry;
    out[3 * n + 2] = rz;
}

// ---------------------------------------------------------------------------
extern "C" void kernel_launch(void* const* d_in, const int* in_sizes, int n_in,
                              void* d_out, int out_size) {
    const float* org = (const float*)d_in[0];
    const float* trg = (const float*)d_in[1];
    float* out = (float*)d_out;

    reduce_kernel<<<dim3(NBLK, NSENS), 256>>>(org, trg);
    adam_kernel<<<1, 32>>>(out);
}

// round 8
// speedup vs baseline: 1.0798x; 1.0798x over previous
#include <cuda_runtime.h>
#include <cstdint>

// ============================================================================
// SensorCalibration. R8: r-monomial reformulation of the contraction:
//   F:C = c*tr(F) + s*(bF.k) + (1-c)*(kT QF k),  k = r/|r|
// evaluated in unnormalized r so that monomials + BR + QR (51 packed slots)
// have NO dependency on rsqrt/sin/cos -> fills the MUFU latency window that
// R7 showed to be the binding bubble. C matrix never built.
// R7: 104.3us (adam 90.9, issue 41%).
// ============================================================================

#define NSENS 17
#define NT    16384
#define ROWLEN (NSENS * 9)
#define NBLK  8
#define NITER 450

__device__ float gPart[NSENS][NBLK][81];

// ---------------------------------------------------------------------------
// fast approx + packed f32x2 intrinsics
// ---------------------------------------------------------------------------
__device__ __forceinline__ float f_rsqrt(float x) { float r; asm("rsqrt.approx.f32 %0, %1;" : "=f"(r) : "f"(x)); return r; }
__device__ __forceinline__ float f_sin(float x)   { float r; asm("sin.approx.f32 %0, %1;"   : "=f"(r) : "f"(x)); return r; }
__device__ __forceinline__ float f_cos(float x)   { float r; asm("cos.approx.f32 %0, %1;"   : "=f"(r) : "f"(x)); return r; }
__device__ __forceinline__ float f_rcp(float x)   { float r; asm("rcp.approx.f32 %0, %1;"   : "=f"(r) : "f"(x)); return r; }
__device__ __forceinline__ float f_ex2(float x)   { float r; asm("ex2.approx.f32 %0, %1;"   : "=f"(r) : "f"(x)); return r; }

typedef unsigned long long u64;
__device__ __forceinline__ u64 pk2(float lo, float hi) {
    u64 r; asm("mov.b64 %0, {%1, %2};" : "=l"(r) : "f"(lo), "f"(hi)); return r;
}
__device__ __forceinline__ void upk2(float& lo, float& hi, u64 v) {
    asm("mov.b64 {%0, %1}, %2;" : "=f"(lo), "=f"(hi) : "l"(v));
}
__device__ __forceinline__ u64 fma2(u64 a, u64 b, u64 c) {
    u64 d; asm("fma.rn.f32x2 %0, %1, %2, %3;" : "=l"(d) : "l"(a), "l"(b), "l"(c)); return d;
}
__device__ __forceinline__ u64 mul2(u64 a, u64 b) {
    u64 d; asm("mul.rn.f32x2 %0, %1, %2;" : "=l"(d) : "l"(a), "l"(b)); return d;
}
__device__ __forceinline__ u64 add2(u64 a, u64 b) {
    u64 d; asm("add.rn.f32x2 %0, %1, %2;" : "=l"(d) : "l"(a), "l"(b)); return d;
}

// ---------------------------------------------------------------------------
// Kernel 1: per-block partials of M[n][jk][il] = sum_t org[t,n,jk]*trg[t,n,il]
// ---------------------------------------------------------------------------
__global__ void reduce_kernel(const float* __restrict__ org,
                              const float* __restrict__ trg) {
    const int n    = blockIdx.y;
    const int base = blockIdx.x * blockDim.x + threadIdx.x;   // 0..2047

    u64   accP[9][4];
    float acc8[9];
#pragma unroll
    for (int j = 0; j < 9; j++) {
#pragma unroll
        for (int p = 0; p < 4; p++) accP[j][p] = 0ull;
        acc8[j] = 0.0f;
    }

#pragma unroll
    for (int kk = 0; kk < 8; kk++) {
        const int t = base + kk * 2048;
        const float* a = org + (size_t)t * ROWLEN + n * 9;
        const float* b = trg + (size_t)t * ROWLEN + n * 9;
        float av[9], bv[9];
#pragma unroll
        for (int i = 0; i < 9; i++) { av[i] = a[i]; bv[i] = b[i]; }
        u64 bp[4];
#pragma unroll
        for (int p = 0; p < 4; p++) bp[p] = pk2(bv[2 * p], bv[2 * p + 1]);
#pragma unroll
        for (int j = 0; j < 9; j++) {
            u64 ad = pk2(av[j], av[j]);
#pragma unroll
            for (int p = 0; p < 4; p++) accP[j][p] = fma2(ad, bp[p], accP[j][p]);
            acc8[j] = fmaf(av[j], bv[8], acc8[j]);
        }
    }

    const int lane = threadIdx.x & 31;
    const int wid  = threadIdx.x >> 5;
    __shared__ float sW[8][81];
#pragma unroll
    for (int j = 0; j < 9; j++) {
#pragma unroll
        for (int p = 0; p < 4; p++) {
            u64 v = accP[j][p];
#pragma unroll
            for (int d = 16; d >= 1; d >>= 1)
                v = add2(v, __shfl_xor_sync(0xFFFFFFFFu, v, d));
            if (lane == 0) {
                float lo, hi; upk2(lo, hi, v);
                sW[wid][j * 9 + 2 * p]     = lo;
                sW[wid][j * 9 + 2 * p + 1] = hi;
            }
        }
        float s8 = acc8[j];
#pragma unroll
        for (int d = 16; d >= 1; d >>= 1)
            s8 += __shfl_xor_sync(0xFFFFFFFFu, s8, d);
        if (lane == 0) sW[wid][j * 9 + 8] = s8;
    }
    __syncthreads();
    if (threadIdx.x < 81) {
        float s = 0.0f;
#pragma unroll
        for (int w = 0; w < 8; w++) s += sW[w][threadIdx.x];
        gPart[n][blockIdx.x][threadIdx.x] = s;
    }
}

// ---------------------------------------------------------------------------
// Threefry2x32-20, key (0,1), partitionable path: bits = o0 ^ o1.
// ---------------------------------------------------------------------------
__device__ __forceinline__ uint32_t rotl32(uint32_t v, uint32_t d) {
    return (v << d) | (v >> (32u - d));
}

__device__ void threefry_01(uint32_t x0, uint32_t x1, uint32_t& o0, uint32_t& o1) {
    const uint32_t k0 = 0u, k1 = 1u;
    const uint32_t k2 = k0 ^ k1 ^ 0x1BD11BDAu;
    x0 += k0; x1 += k1;
    x0 += x1; x1 = rotl32(x1, 13); x1 ^= x0;
    x0 += x1; x1 = rotl32(x1, 15); x1 ^= x0;
    x0 += x1; x1 = rotl32(x1, 26); x1 ^= x0;
    x0 += x1; x1 = rotl32(x1,  6); x1 ^= x0;
    x0 += k1; x1 += k2 + 1u;
    x0 += x1; x1 = rotl32(x1, 17); x1 ^= x0;
    x0 += x1; x1 = rotl32(x1, 29); x1 ^= x0;
    x0 += x1; x1 = rotl32(x1, 16); x1 ^= x0;
    x0 += x1; x1 = rotl32(x1, 24); x1 ^= x0;
    x0 += k2; x1 += k0 + 2u;
    x0 += x1; x1 = rotl32(x1, 13); x1 ^= x0;
    x0 += x1; x1 = rotl32(x1, 15); x1 ^= x0;
    x0 += x1; x1 = rotl32(x1, 26); x1 ^= x0;
    x0 += x1; x1 = rotl32(x1,  6); x1 ^= x0;
    x0 += k0; x1 += k1 + 3u;
    x0 += x1; x1 = rotl32(x1, 17); x1 ^= x0;
    x0 += x1; x1 = rotl32(x1, 29); x1 ^= x0;
    x0 += x1; x1 = rotl32(x1, 16); x1 ^= x0;
    x0 += x1; x1 = rotl32(x1, 24); x1 ^= x0;
    x0 += k1; x1 += k2 + 4u;
    x0 += x1; x1 = rotl32(x1, 13); x1 ^= x0;
    x0 += x1; x1 = rotl32(x1, 15); x1 ^= x0;
    x0 += x1; x1 = rotl32(x1, 26); x1 ^= x0;
    x0 += x1; x1 = rotl32(x1,  6); x1 ^= x0;
    x0 += k2; x1 += k0 + 5u;
    o0 = x0; o1 = x1;
}

__device__ float ang_init(int f) {
    uint32_t o0, o1;
    threefry_01(0u, (uint32_t)f, o0, o1);
    uint32_t bits = o0 ^ o1;
    uint32_t fb = (bits >> 9) | 0x3F800000u;
    return __uint_as_float(fb) - 1.0f;
}

// ---------------------------------------------------------------------------
// Kernel 2: 450 Adam iterations, one thread per sensor.
// Functional pairs (lo,hi): (T,Wx) (Wy,Wz) (S00,S01) (S02,S11) (S12,S22).
// Each F: 9-vector over j=3k+l (with -2*lw folded). Decomposition:
//   F:C = c*a0F + (s*inv)*(bF.r) + ((1-c)*inv^2)*(r^T QF r)
// with a0F = F0+F4+F8, bF = (F7-F5, F2-F6, F3-F1),
//      QF = [F0, F1+F3, F2+F6, F4, F5+F7, F8] over monos [xx,xy,xz,yy,yz,zz].
// Then Sr = S r, wr = w.r, rSr = r.Sr,
//   A = alpha*inv = -si*tD + (c-si)*wr*inv2 + (0.5s - o*inv)*rSr*inv3,
//   g = r*A + si*w + oi2*Sr   (oi2 = o*inv2; == (o/th)*v with v = S k).
// ---------------------------------------------------------------------------
__global__ void __launch_bounds__(32, 1) adam_kernel(float* __restrict__ out) {
    const int n = threadIdx.x;

    // tab.x = lr_t * 0.1 / (1-0.9^t),  tab.y = 0.001 / (1-0.999^t)
    __shared__ float2 sTab[NITER];
    {
        const float l2_09   = -0.15200309344504997f;
        const float l2_0999 = -0.0014434504088372195f;
        for (int t = threadIdx.x; t < NITER; t += 32) {
            float tf = (float)(t + 1);
            float p1 = f_ex2(tf * l2_09);
            float p2 = f_ex2(tf * l2_0999);
            float lr = (t < 150) ? 0.01f : ((t < 300) ? 0.009f : 0.0081f);
            sTab[t].x = lr * 0.1f * f_rcp(1.0f - p1);
            sTab[t].y = 0.001f * f_rcp(1.0f - p2);
        }
    }
    __syncwarp();

    if (n >= NSENS) return;

    double Md[81];
#pragma unroll
    for (int e = 0; e < 81; e++) {
        double s = 0.0;
#pragma unroll
        for (int b = 0; b < NBLK; b++) s += (double)gPart[n][b][e];
        Md[e] = s;
    }

#define MSF(p, k, q, l) \
    (-20.0f * (float)(Md[(3*(p)+(k))*9 + 3*(q)+(l)] + Md[(3*(k)+(p))*9 + 3*(l)+(q)]))

    // 10 functional 9-vectors (prologue-only; spills here are harmless)
    float Fv[10][9];
#pragma unroll
    for (int k = 0; k < 3; k++)
#pragma unroll
        for (int l = 0; l < 3; l++) {
            int j = 3 * k + l;
            Fv[0][j] = MSF(0,k,0,l) + MSF(1,k,1,l) + MSF(2,k,2,l);   // T
            Fv[1][j] = MSF(2,k,1,l) - MSF(1,k,2,l);                  // Wx
            Fv[2][j] = MSF(0,k,2,l) - MSF(2,k,0,l);                  // Wy
            Fv[3][j] = MSF(1,k,0,l) - MSF(0,k,1,l);                  // Wz
            Fv[4][j] = 2.0f * MSF(0,k,0,l);                          // S00
            Fv[5][j] = MSF(0,k,1,l) + MSF(1,k,0,l);                  // S01
            Fv[6][j] = MSF(0,k,2,l) + MSF(2,k,0,l);                  // S02
            Fv[7][j] = 2.0f * MSF(1,k,1,l);                          // S11
            Fv[8][j] = MSF(1,k,2,l) + MSF(2,k,1,l);                  // S12
            Fv[9][j] = 2.0f * MSF(2,k,2,l);                          // S22
        }
#undef MSF

    // packed per-pair coefficient sets
    u64 A0[5], BRc[5][3], QRc[5][6];
#pragma unroll
    for (int p = 0; p < 5; p++) {
        const float* lo = Fv[2 * p];
        const float* hi = Fv[2 * p + 1];
        A0[p]     = pk2(lo[0] + lo[4] + lo[8], hi[0] + hi[4] + hi[8]);
        BRc[p][0] = pk2(lo[7] - lo[5], hi[7] - hi[5]);
        BRc[p][1] = pk2(lo[2] - lo[6], hi[2] - hi[6]);
        BRc[p][2] = pk2(lo[3] - lo[1], hi[3] - hi[1]);
        QRc[p][0] = pk2(lo[0],         hi[0]);           // xx
        QRc[p][1] = pk2(lo[1] + lo[3], hi[1] + hi[3]);   // xy
        QRc[p][2] = pk2(lo[2] + lo[6], hi[2] + hi[6]);   // xz
        QRc[p][3] = pk2(lo[4],         hi[4]);           // yy
        QRc[p][4] = pk2(lo[5] + lo[7], hi[5] + hi[7]);   // yz
        QRc[p][5] = pk2(lo[8],         hi[8]);           // zz
    }

    float rx = ang_init(3 * n + 0);
    float ry = ang_init(3 * n + 1);
    float rz = ang_init(3 * n + 2);
    float Mx = 0.f, My = 0.f, Mz = 0.f;    // m / 0.1
    float Vx = 0.f, Vy = 0.f, Vz = 0.f;    // v / 0.001

#pragma unroll 1
    for (int it = 0; it < NITER; it++) {
        float2 tab = sTab[it];

        float th2 = fmaxf(fmaf(rx, rx, fmaf(ry, ry, rz * rz)), 1e-24f);
        float inv = f_rsqrt(th2);
        float th  = th2 * inv;
        float s = f_sin(th);
        float c = f_cos(th);

        // ---- MUFU-independent block: monomials, BR, QR (fills MUFU latency)
        u64 Rdx = pk2(rx, rx), Rdy = pk2(ry, ry), Rdz = pk2(rz, rz);
        u64 Mxx = mul2(Rdx, Rdx), Mxy = mul2(Rdx, Rdy), Mxz = mul2(Rdx, Rdz);
        u64 Myy = mul2(Rdy, Rdy), Myz = mul2(Rdy, Rdz), Mzz = mul2(Rdz, Rdz);

        u64 BR[5], QR[5];
#pragma unroll
        for (int p = 0; p < 5; p++)
            BR[p] = fma2(BRc[p][2], Rdz,
                    fma2(BRc[p][1], Rdy, mul2(BRc[p][0], Rdx)));
#pragma unroll
        for (int p = 0; p < 5; p++)
            QR[p] = fma2(QRc[p][5], Mzz,
                    fma2(QRc[p][4], Myz,
                    fma2(QRc[p][3], Myy,
                    fma2(QRc[p][2], Mxz,
                    fma2(QRc[p][1], Mxy, mul2(QRc[p][0], Mxx))))));

        // ---- combine with trig
        float o    = 1.0f - c;
        float si   = s * inv;
        float inv2 = inv * inv;
        float oi2  = o * inv2;
        u64 Cdup = pk2(c, c), SId = pk2(si, si), OId = pk2(oi2, oi2);

        float tD, wx, wy, wz, S00, S01, S02, S11, S12, S22;
        {
            u64 f0 = fma2(OId, QR[0], fma2(SId, BR[0], mul2(Cdup, A0[0])));
            u64 f1 = fma2(OId, QR[1], fma2(SId, BR[1], mul2(Cdup, A0[1])));
            u64 f2 = fma2(OId, QR[2], fma2(SId, BR[2], mul2(Cdup, A0[2])));
            u64 f3 = fma2(OId, QR[3], fma2(SId, BR[3], mul2(Cdup, A0[3])));
            u64 f4 = fma2(OId, QR[4], fma2(SId, BR[4], mul2(Cdup, A0[4])));
            upk2(tD,  wx,  f0);
            upk2(wy,  wz,  f1);
            upk2(S00, S01, f2);
            upk2(S02, S11, f3);
            upk2(S12, S22, f4);
        }

        float Srx = fmaf(S00, rx, fmaf(S01, ry, S02 * rz));
        float Sry = fmaf(S01, rx, fmaf(S11, ry, S12 * rz));
        float Srz = fmaf(S02, rx, fmaf(S12, ry, S22 * rz));
        float wr  = fmaf(wx, rx, fmaf(wy, ry, wz * rz));
        float rSr = fmaf(rx, Srx, fmaf(ry, Sry, rz * Srz));

        float oi   = o * inv;
        float inv3 = inv2 * inv;
        float beta = fmaf(0.5f, s, -oi);
        float A = fmaf(-si, tD,
                  fmaf((c - si) * inv2, wr, beta * (rSr * inv3)));

        float gx = fmaf(rx, A, fmaf(si, wx, oi2 * Srx));
        float gy = fmaf(ry, A, fmaf(si, wy, oi2 * Sry));
        float gz = fmaf(rz, A, fmaf(si, wz, oi2 * Srz));

        Mx = fmaf(0.9f, Mx, gx);
        My = fmaf(0.9f, My, gy);
        Mz = fmaf(0.9f, Mz, gz);
        Vx = fmaf(0.999f, Vx, gx * gx);
        Vy = fmaf(0.999f, Vy, gy * gy);
        Vz = fmaf(0.999f, Vz, gz * gz);

        float rsx = f_rsqrt(fmaf(Vx, tab.y, 1e-30f));
        float rsy = f_rsqrt(fmaf(Vy, tab.y, 1e-30f));
        float rsz = f_rsqrt(fmaf(Vz, tab.y, 1e-30f));
        rx = fmaf(-(tab.x * Mx), rsx, rx);
        ry = fmaf(-(tab.x * My), rsy, ry);
        rz = fmaf(-(tab.x * Mz), rsz, rz);
    }

    out[3 * n + 0] = rx;
    out[3 * n + 1] = ry;
    out[3 * n + 2] = rz;
}

// ---------------------------------------------------------------------------
extern "C" void kernel_launch(void* const* d_in, const int* in_sizes, int n_in,
                              void* d_out, int out_size) {
    const float* org = (const float*)d_in[0];
    const float* trg = (const float*)d_in[1];
    float* out = (float*)d_out;

    reduce_kernel<<<dim3(NBLK, NSENS), 256>>>(org, trg);
    adam_kernel<<<1, 32>>>(out);
}